// round 7
// baseline (speedup 1.0000x reference)
#include <cuda_runtime.h>
#include <cuda_bf16.h>

// Elementwise fused: out = (x + 2) + (x * 3) - (x - 1) * (x / 2)
//                       == fma(x, fma(-0.5, x, 4.5), 2)
// 8192 x 16384 fp32 = 134217728 elements = 33554432 float4s.
// Grid-stride, 10 front-batched LDG.128 per thread (MLP=10, ~48 regs,
// 5 CTAs/SM), evict-first hints. Probing the MLP/occupancy optimum
// between UNROLL=8 (best so far, 150.9us) and UNROLL=16 (152.7us).

__device__ __forceinline__ float fuse1(float v) {
    return fmaf(v, fmaf(-0.5f, v, 4.5f), 2.0f);
}

__device__ __forceinline__ float4 fuse4(float4 v) {
    float4 r;
    r.x = fuse1(v.x);
    r.y = fuse1(v.y);
    r.z = fuse1(v.z);
    r.w = fuse1(v.w);
    return r;
}

template <int UNROLL>
__global__ void fused_elemwise_kernel(const float4* __restrict__ x,
                                      float4* __restrict__ out,
                                      int n4) {
    int stride = gridDim.x * blockDim.x;
    int base = blockIdx.x * blockDim.x + threadIdx.x;

    if (base + (UNROLL - 1) * stride < n4) {
        float4 v[UNROLL];
#pragma unroll
        for (int k = 0; k < UNROLL; k++)
            v[k] = __ldcs(&x[base + k * stride]);   // front-batched, MLP=UNROLL
#pragma unroll
        for (int k = 0; k < UNROLL; k++)
            __stcs(&out[base + k * stride], fuse4(v[k]));
    } else {
        for (int i = base; i < n4; i += stride)
            __stcs(&out[i], fuse4(__ldcs(&x[i])));
    }
}

__global__ void fused_elemwise_tail(const float* __restrict__ x,
                                    float* __restrict__ out,
                                    int start, int n) {
    int i = start + blockIdx.x * blockDim.x + threadIdx.x;
    if (i < n) out[i] = fuse1(x[i]);
}

extern "C" void kernel_launch(void* const* d_in, const int* in_sizes, int n_in,
                              void* d_out, int out_size) {
    const float* x = (const float*)d_in[0];
    float* out = (float*)d_out;
    int n = in_sizes[0];

    int n4 = n / 4;
    if (n4 > 0) {
        constexpr int UNROLL = 10;
        const int threads = 256;
        int total_threads = (n4 + UNROLL - 1) / UNROLL;
        int blocks = (total_threads + threads - 1) / threads;
        fused_elemwise_kernel<UNROLL><<<blocks, threads>>>(
            (const float4*)x, (float4*)out, n4);
    }
    int rem = n - n4 * 4;
    if (rem > 0) {
        fused_elemwise_tail<<<1, 256>>>(x, out, n4 * 4, n);
    }
}

// round 8
// speedup vs baseline: 1.0115x; 1.0115x over previous
#include <cuda_runtime.h>
#include <cuda_bf16.h>

// Elementwise fused: out = (x + 2) + (x * 3) - (x - 1) * (x / 2)
// 8192 x 16384 fp32 = 134217728 elements = 33554432 float4s.
// FINAL: measured optimum on GB300. Grid-stride, 8 front-batched LDG.128
// per thread (MLP=8), evict-first cache hints, grid=16384 x 256.
// HBM-bound at ~7.1 TB/s combined read+write (~85% DRAM-active) — the
// bus-turnaround roofline. Measured sweep: UNROLL 4/8/10/16 ->
// 152.3/150.9/154.6/152.7 us; persistent and block-contiguous variants
// regressed.

__device__ __forceinline__ float fuse1(float v) {
    return (v + 2.0f) + (v * 3.0f) - (v - 1.0f) * (v * 0.5f);
}

__device__ __forceinline__ float4 fuse4(float4 v) {
    float4 r;
    r.x = fuse1(v.x);
    r.y = fuse1(v.y);
    r.z = fuse1(v.z);
    r.w = fuse1(v.w);
    return r;
}

template <int UNROLL>
__global__ void fused_elemwise_kernel(const float4* __restrict__ x,
                                      float4* __restrict__ out,
                                      int n4) {
    int stride = gridDim.x * blockDim.x;
    int base = blockIdx.x * blockDim.x + threadIdx.x;

    int last = base + (UNROLL - 1) * stride;
    if (last < n4) {
        float4 v[UNROLL];
#pragma unroll
        for (int k = 0; k < UNROLL; k++)
            v[k] = __ldcs(&x[base + k * stride]);   // front-batched, MLP=UNROLL
#pragma unroll
        for (int k = 0; k < UNROLL; k++)
            __stcs(&out[base + k * stride], fuse4(v[k]));
    } else {
        for (int i = base; i < n4; i += stride)
            __stcs(&out[i], fuse4(__ldcs(&x[i])));
    }
}

__global__ void fused_elemwise_tail(const float* __restrict__ x,
                                    float* __restrict__ out,
                                    int start, int n) {
    int i = start + blockIdx.x * blockDim.x + threadIdx.x;
    if (i < n) out[i] = fuse1(x[i]);
}

extern "C" void kernel_launch(void* const* d_in, const int* in_sizes, int n_in,
                              void* d_out, int out_size) {
    const float* x = (const float*)d_in[0];
    float* out = (float*)d_out;
    int n = in_sizes[0];

    int n4 = n / 4;
    if (n4 > 0) {
        constexpr int UNROLL = 8;
        const int threads = 256;
        int total_threads = (n4 + UNROLL - 1) / UNROLL;
        int blocks = (total_threads + threads - 1) / threads;
        fused_elemwise_kernel<UNROLL><<<blocks, threads>>>(
            (const float4*)x, (float4*)out, n4);
    }
    int rem = n - n4 * 4;
    if (rem > 0) {
        fused_elemwise_tail<<<1, 256>>>(x, out, n4 * 4, n);
    }
}

// round 9
// speedup vs baseline: 1.0160x; 1.0045x over previous
#include <cuda_runtime.h>
#include <cuda_bf16.h>

// Elementwise fused: out = (x + 2) + (x * 3) - (x - 1) * (x / 2)
// 8192 x 16384 fp32 = 134217728 elements = 16777216 float8s.
// Blackwell 256-bit global ops: ld.global.cs.v8.f32 / st.global.cs.v8.f32
// (LDG.E.256/STG.E.256) — half the memory instructions vs float4 at the
// same bytes/thread. Grid-stride, 4 front-batched v8 loads per thread
// (same 1KB/thread as the measured UNROLL=8 float4 optimum), grid=16384.

struct __align__(32) f8 { float v[8]; };

__device__ __forceinline__ f8 ldg256_cs(const f8* p) {
    f8 r;
    asm volatile(
        "ld.global.cs.v8.f32 {%0,%1,%2,%3,%4,%5,%6,%7}, [%8];"
        : "=f"(r.v[0]), "=f"(r.v[1]), "=f"(r.v[2]), "=f"(r.v[3]),
          "=f"(r.v[4]), "=f"(r.v[5]), "=f"(r.v[6]), "=f"(r.v[7])
        : "l"(p));
    return r;
}

__device__ __forceinline__ void stg256_cs(f8* p, const f8& r) {
    asm volatile(
        "st.global.cs.v8.f32 [%0], {%1,%2,%3,%4,%5,%6,%7,%8};"
        :: "l"(p),
           "f"(r.v[0]), "f"(r.v[1]), "f"(r.v[2]), "f"(r.v[3]),
           "f"(r.v[4]), "f"(r.v[5]), "f"(r.v[6]), "f"(r.v[7])
        : "memory");
}

__device__ __forceinline__ float fuse1(float v) {
    return (v + 2.0f) + (v * 3.0f) - (v - 1.0f) * (v * 0.5f);
}

__device__ __forceinline__ f8 fuse8(f8 a) {
    f8 r;
#pragma unroll
    for (int i = 0; i < 8; i++) r.v[i] = fuse1(a.v[i]);
    return r;
}

template <int UNROLL>
__global__ void fused_elemwise_kernel(const f8* __restrict__ x,
                                      f8* __restrict__ out,
                                      int n8) {
    int stride = gridDim.x * blockDim.x;
    int base = blockIdx.x * blockDim.x + threadIdx.x;

    if (base + (UNROLL - 1) * stride < n8) {
        f8 v[UNROLL];
#pragma unroll
        for (int k = 0; k < UNROLL; k++)
            v[k] = ldg256_cs(&x[base + k * stride]);   // front-batched
#pragma unroll
        for (int k = 0; k < UNROLL; k++)
            stg256_cs(&out[base + k * stride], fuse8(v[k]));
    } else {
        for (int i = base; i < n8; i += stride)
            stg256_cs(&out[i], fuse8(ldg256_cs(&x[i])));
    }
}

__global__ void fused_elemwise_tail(const float* __restrict__ x,
                                    float* __restrict__ out,
                                    int start, int n) {
    int i = start + blockIdx.x * blockDim.x + threadIdx.x;
    if (i < n) out[i] = fuse1(x[i]);
}

extern "C" void kernel_launch(void* const* d_in, const int* in_sizes, int n_in,
                              void* d_out, int out_size) {
    const float* x = (const float*)d_in[0];
    float* out = (float*)d_out;
    int n = in_sizes[0];

    int n8 = n / 8;
    if (n8 > 0) {
        constexpr int UNROLL = 4;   // 4 x 32B = same bytes/thread as 8 x 16B
        const int threads = 256;
        int total_threads = (n8 + UNROLL - 1) / UNROLL;
        int blocks = (total_threads + threads - 1) / threads;
        fused_elemwise_kernel<UNROLL><<<blocks, threads>>>(
            (const f8*)x, (f8*)out, n8);
    }
    int rem = n - n8 * 8;
    if (rem > 0) {
        fused_elemwise_tail<<<1, 256>>>(x, out, n8 * 8, n);
    }
}